// round 3
// baseline (speedup 1.0000x reference)
#include <cuda_runtime.h>
#include <cuda_bf16.h>

// z_1: [B,16] fp32 (64B rows). Need cols 0..4 -> float4 at row base + scalar
// at +16B (same 32B sector; DRAM fetches the 64B row regardless).
// dir: [B,8] fp32 (32B rows). We pay one full sector per row no matter what,
// so load the WHOLE row up front (2x float4) and select in registers --
// removes the compute->gather serialization that was capping DRAM at 86%.
// 2 rows per thread, all loads front-batched, float2 coalesced store.

__device__ __forceinline__ float zone_and_pick(
    float lx, float ly, float rx, float ry, float4 d0, float4 d1)
{
    float dx = rx - lx;
    float dy = -(ry - ly);

    float phi = atan2f(dy, dx) * 57.29577951308232f;
    if (phi < 0.0f) phi += 360.0f;

    int pcs = (90 + (int)phi) % 360;        // truncation == floor (phi >= 0)
    int zone = ((pcs + 11) / 22) & 7;       // area_angle=22, half=11 (exact)

    // binary select tree over the 8 preloaded dir values
    float s01 = (zone & 1) ? d0.y : d0.x;
    float s23 = (zone & 1) ? d0.w : d0.z;
    float s45 = (zone & 1) ? d1.y : d1.x;
    float s67 = (zone & 1) ? d1.w : d1.z;
    float lo  = (zone & 2) ? s23 : s01;
    float hi  = (zone & 2) ? s67 : s45;
    return (zone & 4) ? hi : lo;
}

__global__ __launch_bounds__(256) void slope_valuation_kernel(
    const float4* __restrict__ z4,    // z_1 as float4 (4 per 16-float row)
    const float*  __restrict__ z,     // z_1 scalar view
    const float4* __restrict__ dir4,  // dir as float4 (2 per 8-float row)
    float2*       __restrict__ out2,  // out as float2
    int n2)                           // number of row-pairs (B/2)
{
    int t = blockIdx.x * blockDim.x + threadIdx.x;
    if (t >= n2) return;

    size_t r0 = (size_t)t * 2;        // first row of this thread's pair
    size_t r1 = r0 + 1;

    // ---- front-batch ALL loads (6 independent LDGs -> high MLP) ----
    float4 va  = __ldg(&z4[r0 * 4]);
    float4 vb  = __ldg(&z4[r1 * 4]);
    float  rya = __ldg(&z[r0 * 16 + 4]);
    float  ryb = __ldg(&z[r1 * 16 + 4]);
    float4 d0a = __ldg(&dir4[r0 * 2]);
    float4 d1a = __ldg(&dir4[r0 * 2 + 1]);
    float4 d0b = __ldg(&dir4[r1 * 2]);
    float4 d1b = __ldg(&dir4[r1 * 2 + 1]);

    float pa = zone_and_pick(va.y, va.z, va.w, rya, d0a, d1a);
    float pb = zone_and_pick(vb.y, vb.z, vb.w, ryb, d0b, d1b);

    float2 o;
    o.x = (va.x != 0.0f) ? pa : 0.0f;   // col0 = has_line
    o.y = (vb.x != 0.0f) ? pb : 0.0f;
    out2[t] = o;
}

// Tail kernel for odd B (not hit for B=4M, kept for generality)
__global__ void slope_valuation_tail(
    const float4* __restrict__ z4, const float* __restrict__ z,
    const float4* __restrict__ dir4, float* __restrict__ out, int i)
{
    float4 v  = __ldg(&z4[(size_t)i * 4]);
    float  ry = __ldg(&z[(size_t)i * 16 + 4]);
    float4 d0 = __ldg(&dir4[(size_t)i * 2]);
    float4 d1 = __ldg(&dir4[(size_t)i * 2 + 1]);
    float  p  = zone_and_pick(v.y, v.z, v.w, ry, d0, d1);
    out[i] = (v.x != 0.0f) ? p : 0.0f;
}

extern "C" void kernel_launch(void* const* d_in, const int* in_sizes, int n_in,
                              void* d_out, int out_size)
{
    const float* z_1 = (const float*)d_in[0];   // [B,16] fp32
    const float* dir = (const float*)d_in[1];   // [B,8]  fp32
    float* out = (float*)d_out;                 // [B]    fp32

    int n  = in_sizes[0] / 16;                  // B rows
    int n2 = n / 2;

    int threads = 256;
    int blocks = (n2 + threads - 1) / threads;
    slope_valuation_kernel<<<blocks, threads>>>(
        (const float4*)z_1, z_1, (const float4*)dir, (float2*)out, n2);

    if (n & 1) {
        slope_valuation_tail<<<1, 1>>>(
            (const float4*)z_1, z_1, (const float4*)dir, out, n - 1);
    }
}

// round 4
// speedup vs baseline: 1.0195x; 1.0195x over previous
#include <cuda_runtime.h>
#include <cuda_bf16.h>

// z_1: [B,16] fp32 (64B rows). Need cols 0..4. Loaded as two float4s at row
// base (+0, +16B) -- both in the same 32B sector, so one DRAM sector request;
// DRAM fetches the full 64B row either way (granularity measured in R2).
// dir: [B,8] fp32 = one 32B sector per row. We pay for the whole sector no
// matter which element we gather, so preload the entire row (2x float4)
// UNCONDITIONALLY, in parallel with the z loads, and select in registers.
// -> 4 independent LDGs per thread, no compute->gather serialization.
// 1 row per thread keeps regs ~28 and occupancy high (the R3 regression was
// the 2-row batching pushing regs to 40 / occ to 62%).

__global__ __launch_bounds__(256) void slope_valuation_kernel(
    const float4* __restrict__ z4,    // z_1 as float4 (4 per 16-float row)
    const float4* __restrict__ dir4,  // dir as float4 (2 per 8-float row)
    float*        __restrict__ out,   // [B]
    int n)
{
    int i = blockIdx.x * blockDim.x + threadIdx.x;
    if (i >= n) return;

    // ---- 4 independent streaming loads, all issued up front ----
    float4 v0 = __ldcs(&z4[(size_t)i * 4]);      // line, lx, ly, rx
    float4 v1 = __ldcs(&z4[(size_t)i * 4 + 1]);  // ry, ... (same sector as v0)
    float4 d0 = __ldcs(&dir4[(size_t)i * 2]);    // dir[0..3]
    float4 d1 = __ldcs(&dir4[(size_t)i * 2 + 1]);// dir[4..7]

    float dx = v0.w - v0.y;          // rx - lx
    float dy = -(v1.x - v0.z);       // -(ry - ly)

    float phi = atan2f(dy, dx) * 57.29577951308232f;
    if (phi < 0.0f) phi += 360.0f;

    int pcs  = (90 + (int)phi) % 360;   // truncation == floor (phi >= 0)
    int zone = ((pcs + 11) / 22) & 7;   // area_angle=22, half=11 (exact)

    // binary select tree over the 8 preloaded dir values
    float s01 = (zone & 1) ? d0.y : d0.x;
    float s23 = (zone & 1) ? d0.w : d0.z;
    float s45 = (zone & 1) ? d1.y : d1.x;
    float s67 = (zone & 1) ? d1.w : d1.z;
    float lo  = (zone & 2) ? s23 : s01;
    float hi  = (zone & 2) ? s67 : s45;
    float picked = (zone & 4) ? hi : lo;

    __stcs(&out[i], (v0.x != 0.0f) ? picked : 0.0f);
}

extern "C" void kernel_launch(void* const* d_in, const int* in_sizes, int n_in,
                              void* d_out, int out_size)
{
    const float* z_1 = (const float*)d_in[0];   // [B,16] fp32
    const float* dir = (const float*)d_in[1];   // [B,8]  fp32
    float* out = (float*)d_out;                 // [B]    fp32

    int n = in_sizes[0] / 16;                   // B rows

    int threads = 256;
    int blocks = (n + threads - 1) / threads;
    slope_valuation_kernel<<<blocks, threads>>>(
        (const float4*)z_1, (const float4*)dir, out, n);
}

// round 7
// speedup vs baseline: 1.0238x; 1.0041x over previous
#include <cuda_runtime.h>
#include <cuda_bf16.h>

// R2 body (best so far: 58.56us kernel, DRAM 86.3%) made persistent.
//
// z_1: [B,16] fp32 (64B rows): float4 at row base (cols 0-3) + scalar col 4,
//      both in the row's first 32B sector (DRAM fetches the 64B row anyway —
//      granularity measured in R2: total traffic == 400 MB exactly).
// dir: [B,8] fp32: dependent 4B gather (one 32B sector/row regardless).
// out: [B] fp32 coalesced store.
//
// Single change this round: persistent grid-stride with exactly one
// full-residency wave (152 SMs x 8 blocks x 256 thr), eliminating the ~10
// wave transitions of the 15625-block launch whose pipeline drains were the
// best remaining explanation for DRAM sitting at 86% instead of ~95%.

__global__ __launch_bounds__(256) void slope_valuation_kernel(
    const float4* __restrict__ z4,   // z_1 as float4 (4 per 16-float row)
    const float*  __restrict__ z,    // z_1 scalar view
    const float*  __restrict__ dir,  // [B, 8]
    float*        __restrict__ out,  // [B]
    int n)
{
    int stride = gridDim.x * blockDim.x;
    for (int i = blockIdx.x * blockDim.x + threadIdx.x; i < n; i += stride) {
        // one 16B load covering cols 0..3 (line, lx, ly, rx)
        float4 v = __ldcs(&z4[(size_t)i * 4]);
        // col 4 (ry), same 32B sector as the float4
        float ry = __ldcs(&z[(size_t)i * 16 + 4]);

        float dx = v.w - v.y;
        float dy = -(ry - v.z);

        float phi = atan2f(dy, dx) * 57.29577951308232f;
        if (phi < 0.0f) phi += 360.0f;

        int pcs  = (90 + (int)phi) % 360;   // truncation == floor (phi >= 0)
        int zone = ((pcs + 11) / 22) & 7;   // area_angle=22, half=11 (exact)

        float picked = __ldcs(&dir[(size_t)i * 8 + zone]);
        __stcs(&out[i], (v.x != 0.0f) ? picked : 0.0f);
    }
}

extern "C" void kernel_launch(void* const* d_in, const int* in_sizes, int n_in,
                              void* d_out, int out_size)
{
    const float* z_1 = (const float*)d_in[0];   // [B,16] fp32
    const float* dir = (const float*)d_in[1];   // [B,8]  fp32
    float* out = (float*)d_out;                 // [B]    fp32

    int n = in_sizes[0] / 16;                   // B rows

    // Exactly one full-residency wave: 152 SMs x 8 CTAs (256 thr, ~22 regs
    // -> 2048 threads/SM resident). Grid-stride loop covers all rows.
    int threads = 256;
    int blocks  = 152 * 8;
    int max_blocks = (n + threads - 1) / threads;
    if (blocks > max_blocks) blocks = max_blocks;

    slope_valuation_kernel<<<blocks, threads>>>(
        (const float4*)z_1, z_1, dir, out, n);
}

// round 8
// speedup vs baseline: 1.0243x; 1.0005x over previous
#include <cuda_runtime.h>
#include <cuda_bf16.h>

// Best-known ingredients (from R2 vs R3/R4/R7 ablations):
//   - plain multi-wave launch (persistent grid regressed: DRAM 86.3->80.9%)
//   - __ldg, not __ldcs (streaming hint cost 3-5% DRAM busy at equal traffic)
//   - dependent 4B dir gather (full-row preload doubled L1/L2 work, regressed)
// New single variable: 2 rows/thread WITHOUT dir preload, regs pinned <=32 via
// __launch_bounds__(256,8) so occupancy stays at 2048 thr/SM. Front-batches
// 4 independent z loads per thread (MLP_p1 2->4) + 2 independent gathers,
// and writes one coalesced float2.
//
// Traffic floor (measured): 400 MB — z_1 rows fetched at 64B granule (256 MB),
// dir one 32B sector/row (128 MB), out 16 MB. Only lever is DRAM busy%.

__device__ __forceinline__ int zone_of(float lx, float ly, float rx, float ry)
{
    float dx = rx - lx;
    float dy = -(ry - ly);
    float phi = atan2f(dy, dx) * 57.29577951308232f;
    if (phi < 0.0f) phi += 360.0f;
    int pcs = (90 + (int)phi) % 360;    // truncation == floor (phi >= 0)
    return ((pcs + 11) / 22) & 7;       // area_angle=22, half=11 (exact)
}

__global__ __launch_bounds__(256, 8) void slope_valuation_kernel(
    const float4* __restrict__ z4,   // z_1 as float4 (4 per 16-float row)
    const float*  __restrict__ z,    // z_1 scalar view
    const float*  __restrict__ dir,  // [B, 8]
    float2*       __restrict__ out2, // out as float2
    int n2)                          // row pairs (B/2)
{
    int t = blockIdx.x * blockDim.x + threadIdx.x;
    if (t >= n2) return;

    size_t r0 = (size_t)t * 2;
    size_t r1 = r0 + 1;

    // 4 independent front-batched loads (z row pair: 128B contiguous/thread-pair)
    float4 va  = __ldg(&z4[r0 * 4]);          // line, lx, ly, rx  (row 0)
    float  rya = __ldg(&z[r0 * 16 + 4]);      // ry (same 32B sector)
    float4 vb  = __ldg(&z4[r1 * 4]);          // row 1
    float  ryb = __ldg(&z[r1 * 16 + 4]);

    int za = zone_of(va.y, va.z, va.w, rya);
    int zb = zone_of(vb.y, vb.z, vb.w, ryb);

    // two independent gathers (latency of one overlaps compute of the other)
    float pa = __ldg(&dir[r0 * 8 + za]);
    float pb = __ldg(&dir[r1 * 8 + zb]);

    float2 o;
    o.x = (va.x != 0.0f) ? pa : 0.0f;
    o.y = (vb.x != 0.0f) ? pb : 0.0f;
    out2[t] = o;
}

// Tail for odd B (not hit at B=4M)
__global__ void slope_valuation_tail(
    const float4* __restrict__ z4, const float* __restrict__ z,
    const float*  __restrict__ dir, float* __restrict__ out, int i)
{
    float4 v  = __ldg(&z4[(size_t)i * 4]);
    float  ry = __ldg(&z[(size_t)i * 16 + 4]);
    int    zn = zone_of(v.y, v.z, v.w, ry);
    float  p  = __ldg(&dir[(size_t)i * 8 + zn]);
    out[i] = (v.x != 0.0f) ? p : 0.0f;
}

extern "C" void kernel_launch(void* const* d_in, const int* in_sizes, int n_in,
                              void* d_out, int out_size)
{
    const float* z_1 = (const float*)d_in[0];   // [B,16] fp32
    const float* dir = (const float*)d_in[1];   // [B,8]  fp32
    float* out = (float*)d_out;                 // [B]    fp32

    int n  = in_sizes[0] / 16;                  // B rows
    int n2 = n / 2;

    int threads = 256;
    int blocks = (n2 + threads - 1) / threads;
    slope_valuation_kernel<<<blocks, threads>>>(
        (const float4*)z_1, z_1, dir, (float2*)out, n2);

    if (n & 1) {
        slope_valuation_tail<<<1, 1>>>(
            (const float4*)z_1, z_1, dir, out, n - 1);
    }
}